// round 15
// baseline (speedup 1.0000x reference)
#include <cuda_runtime.h>
#include <math.h>

#define BN 32
#define TN 4096
#define UN 256
#define NJ 1024
#define CL 8

// ---------------- static device scratch (no runtime allocation) -------------
// padded by one step row so the t+1 prefetch at t = TN-1 stays in bounds
__device__ float g_Zx[(size_t)(TN + 1) * BN * NJ];   // [t*32+b][j] input projection
__device__ float g_Wp[512 * NJ];                     // packed W: rows 0..255 s-part, 256..511 x-part; col j=g*256+u

// ---------------- helpers ----------------------------------------------------
__device__ __forceinline__ unsigned smem_u32(const void* p) {
    unsigned a;
    asm("{ .reg .u64 t; cvta.to.shared.u64 t, %1; cvt.u32.u64 %0, t; }"
        : "=r"(a) : "l"(p));
    return a;
}
__device__ __forceinline__ unsigned long long pk2(float v) {
    unsigned long long r; unsigned u = __float_as_uint(v);
    asm("mov.b64 %0, {%1, %1};" : "=l"(r) : "r"(u));
    return r;
}
__device__ __forceinline__ unsigned long long pack2(float lo, float hi) {
    unsigned long long r;
    asm("mov.b64 %0, {%1, %2};" : "=l"(r)
        : "r"(__float_as_uint(lo)), "r"(__float_as_uint(hi)));
    return r;
}
__device__ __forceinline__ unsigned long long fma2(unsigned long long a,
                                                   unsigned long long b,
                                                   unsigned long long c) {
    unsigned long long d;
    asm("fma.rn.f32x2 %0, %1, %2, %3;" : "=l"(d) : "l"(a), "l"(b), "l"(c));
    return d;
}
__device__ __forceinline__ float2 upk2(unsigned long long v) {
    unsigned lo, hi;
    asm("mov.b64 {%0, %1}, %2;" : "=r"(lo), "=r"(hi) : "l"(v));
    return make_float2(__uint_as_float(lo), __uint_as_float(hi));
}
__device__ __forceinline__ unsigned mapa_u32(unsigned local, unsigned rank) {
    unsigned r;
    asm("mapa.shared::cluster.u32 %0, %1, %2;" : "=r"(r) : "r"(local), "r"(rank));
    return r;
}
__device__ __forceinline__ void mbar_init(unsigned addr, unsigned cnt) {
    asm volatile("mbarrier.init.shared.b64 [%0], %1;" :: "r"(addr), "r"(cnt) : "memory");
}
__device__ __forceinline__ void mbar_expect_tx(unsigned addr, unsigned bytes) {
    asm volatile("mbarrier.arrive.expect_tx.shared.b64 _, [%0], %1;"
                 :: "r"(addr), "r"(bytes) : "memory");
}
// TMA-style wait: CTA-scope acquire, tight poll, no suspend hint.
__device__ __forceinline__ void mbar_wait(unsigned addr, unsigned parity) {
    asm volatile(
        "{\n\t"
        ".reg .pred P;\n\t"
        "WL_%=:\n\t"
        "mbarrier.try_wait.parity.acquire.cta.shared::cta.b64 P, [%0], %1;\n\t"
        "@!P bra WL_%=;\n\t"
        "}"
        :: "r"(addr), "r"(parity) : "memory");
}
// 16-byte async store to a cluster CTA's SMEM, tx-accounted at remote mbarrier
__device__ __forceinline__ void st_async_v4(unsigned addr, float a, float b,
                                            float c, float d, unsigned rbar) {
    asm volatile(
        "st.async.shared::cluster.mbarrier::complete_tx::bytes.v4.f32 "
        "[%0], {%1, %2, %3, %4}, [%5];"
        :: "r"(addr), "f"(a), "f"(b), "f"(c), "f"(d), "r"(rbar) : "memory");
}
// unified gate nonlinearity: A + B / (1 + exp(s*z))
__device__ __forceinline__ float gatefn(float a, float A, float B) {
    float e = __expf(a);
    float r = __fdividef(B, 1.0f + e);
    return A + r;
}
__device__ __forceinline__ float tanh_fast(float z) {
    float e = __expf(2.0f * z);
    return 1.0f - __fdividef(2.0f, 1.0f + e);
}

// ---------------- alignment rotator (so ncu -s 5 lands on k_rec) ------------
__global__ void k_nop() {}

// ---------------- kernel 0: pack weights ------------------------------------
__global__ __launch_bounds__(256) void k_init(const float* __restrict__ Wf,
                                              const float* __restrict__ Wi,
                                              const float* __restrict__ Wc,
                                              const float* __restrict__ Wo) {
    int idx = blockIdx.x * blockDim.x + threadIdx.x;
    if (idx < 512 * 1024) {
        int k = idx >> 10, j = idx & 1023;
        int g = j >> 8,    u = j & 255;
        const float* W = (g == 0) ? Wf : (g == 1) ? Wi : (g == 2) ? Wc : Wo;
        g_Wp[idx] = W[k * 256 + u];
    }
}

// ---------------- kernel 1: input projection GEMM ---------------------------
__global__ __launch_bounds__(256) void k_gemm(const float* __restrict__ x) {
    __shared__ __align__(16) float As[16][64];
    __shared__ __align__(16) float Bs[16][64];

    const int tid = threadIdx.x;
    const int n0  = blockIdx.x * 64;
    const int m0  = blockIdx.y * 64;
    const int tm  = tid >> 4, tn = tid & 15;
    const int ar  = tid >> 2, akq = tid & 3;
    const int bkr = tid >> 4, bnq = tid & 15;

    const int m_glob = m0 + ar;
    const int bb = m_glob & 31, tt = m_glob >> 5;
    const float* arow = x + ((size_t)bb * TN + tt) * 256;

    unsigned long long a00=0, a01=0, a10=0, a11=0, a20=0, a21=0, a30=0, a31=0;

    float4 av = *(const float4*)(arow + akq * 4);
    float4 bv = *(const float4*)(g_Wp + (size_t)(256 + bkr) * NJ + n0 + bnq * 4);

    for (int k0 = 0; k0 < 256; k0 += 16) {
        __syncthreads();
        As[akq * 4 + 0][ar] = av.x;
        As[akq * 4 + 1][ar] = av.y;
        As[akq * 4 + 2][ar] = av.z;
        As[akq * 4 + 3][ar] = av.w;
        *(float4*)&Bs[bkr][bnq * 4] = bv;
        __syncthreads();

        if (k0 + 16 < 256) {
            av = *(const float4*)(arow + k0 + 16 + akq * 4);
            bv = *(const float4*)(g_Wp + (size_t)(256 + k0 + 16 + bkr) * NJ + n0 + bnq * 4);
        }
        #pragma unroll
        for (int kk = 0; kk < 16; kk++) {
            float4 a = *(const float4*)&As[kk][tm * 4];
            ulonglong2 w = *(const ulonglong2*)&Bs[kk][tn * 4];
            unsigned long long p;
            p = pk2(a.x); a00 = fma2(p, w.x, a00); a01 = fma2(p, w.y, a01);
            p = pk2(a.y); a10 = fma2(p, w.x, a10); a11 = fma2(p, w.y, a11);
            p = pk2(a.z); a20 = fma2(p, w.x, a20); a21 = fma2(p, w.y, a21);
            p = pk2(a.w); a30 = fma2(p, w.x, a30); a31 = fma2(p, w.y, a31);
        }
    }
    float2 lo, hi;
    lo = upk2(a00); hi = upk2(a01);
    *(float4*)(g_Zx + (size_t)(m0 + tm*4 + 0) * NJ + n0 + tn*4) = make_float4(lo.x, lo.y, hi.x, hi.y);
    lo = upk2(a10); hi = upk2(a11);
    *(float4*)(g_Zx + (size_t)(m0 + tm*4 + 1) * NJ + n0 + tn*4) = make_float4(lo.x, lo.y, hi.x, hi.y);
    lo = upk2(a20); hi = upk2(a21);
    *(float4*)(g_Zx + (size_t)(m0 + tm*4 + 2) * NJ + n0 + tn*4) = make_float4(lo.x, lo.y, hi.x, hi.y);
    lo = upk2(a30); hi = upk2(a31);
    *(float4*)(g_Zx + (size_t)(m0 + tm*4 + 3) * NJ + n0 + tn*4) = make_float4(lo.x, lo.y, hi.x, hi.y);
}

// ---------------- kernel 2: persistent recurrence ----------------------------
// R13 base (512 thr, best 8188us). CHANGES: (a) state layout [parity][b][256]
// so 4 consecutive u's of one batch are a contiguous 16B; (b) pushes widened
// to st.async.v4 from 16 pusher lanes -> 16 tx per barrier instead of 64;
// (c) pushers stagger target order to balance per-target last-arrival.
__global__ __launch_bounds__(512, 1) __cluster_dims__(CL, 1, 1)
void k_rec(float* __restrict__ out, const float* __restrict__ h0) {
    __shared__ __align__(16) float Ssm[2][2][256];     // [parity][b][k]
    __shared__ __align__(16) float Zsm[2][16][264];    // [parity][warp][b*128 + jj]
    __shared__ __align__(8)  unsigned long long mbars[2][8];  // [set = p&1][source]

    const int tid  = threadIdx.x;
    const int lane = tid & 31;
    const int wid  = tid >> 5;
    unsigned r;
    asm("mov.u32 %0, %%cluster_ctarank;" : "=r"(r));
    const int team = blockIdx.x >> 3;
    const int b0   = team * 2;
    const int u0   = (int)r * 32;

    const int jq = lane, kbeg = wid * 16;        // matmul: warp = 16-wide k-slice
    const int jj = tid & 127, bb = (tid >> 7) & 1;  // reduce/gate role (tid<256)
    const int gg = jj & 3,    uu = jj >> 2;
    const int jcol = gg * 256 + u0 + uu;
    const size_t c_off = (size_t)BN * TN * UN;

    if (tid < 16) mbar_init(smem_u32(&mbars[tid >> 3][tid & 7]), 1);

    // initial state for step 0 ([b][k] planes)
    if (tid < 256) {
        Ssm[0][0][tid] = h0[(b0 + 0) * 256 + tid];
        Ssm[0][1][tid] = h0[(b0 + 1) * 256 + tid];
    }

    // gate-fn constants (f,i,g: sigmoid; o: tanh)
    const float gA = (gg == 3) ? 1.0f : 0.0f;
    const float gB = (gg == 3) ? -2.0f : 1.0f;
    const float gS = (gg == 3) ? 2.0f : -1.0f;

    // weights -> registers: w[k][m] packs cols (jq+64m, jq+64m+32), k in slice
    unsigned long long w[16][2];
    #pragma unroll
    for (int k = 0; k < 16; k++) {
        const float* row = g_Wp + (size_t)(kbeg + k) * NJ;
        #pragma unroll
        for (int m = 0; m < 2; m++) {
            int jA = jq + 64 * m, jB = jA + 32;
            int cA = (jA & 3) * 256 + u0 + (jA >> 2);
            int cB = (jB & 3) * 256 + u0 + (jB >> 2);
            w[k][m] = pack2(__ldg(row + cA), __ldg(row + cB));
        }
    }

    // remote addressing: one mapa base per rank; offsets are rank-invariant
    const unsigned SsmB = smem_u32(&Ssm[0][0][0]);
    unsigned m0v[8];
    #pragma unroll
    for (int rk = 0; rk < 8; rk++) m0v[rk] = mapa_u32(SsmB, (unsigned)rk);
    const unsigned barDelta = smem_u32(&mbars[0][0]) - SsmB + (unsigned)r * 8;
    // pusher: lanes 0,16 of gate warps; quad base uu = 8*(wid&3) + 4*(lane>>4)
    const int  uq       = 8 * (wid & 3) + 4 * (lane >> 4);
    const unsigned pushOffB = (unsigned)((bb * 256 + u0 + uq) * 4);
    const int  pusherId = ((wid & 7) << 1) | (lane >> 4);   // 0..15 (gate warps)

    const unsigned mywait0 = smem_u32(&mbars[0][wid >> 1]);
    const unsigned mywait1 = smem_u32(&mbars[1][wid >> 1]);
    const bool rearm = (lane == 0) && ((wid & 1) == 0);

    // pre-arm both barrier sets (before cluster barrier -> precedes any push)
    if (rearm) {
        mbar_expect_tx(mywait0, 256);
        mbar_expect_tx(mywait1, 256);
    }

    // per-step incremented pointers
    const float* zxp = g_Zx + (size_t)(b0 + bb) * NJ + jcol;     // += 32*NJ
    float* outH = out + (size_t)(b0 + bb) * TN * UN + (u0 + uu); // += UN

    __syncthreads();
    asm volatile("barrier.cluster.arrive.aligned;" ::: "memory");
    asm volatile("barrier.cluster.wait.aligned;" ::: "memory");

    float zx_cur = (tid < 256) ? __ldcg(zxp) : 0.0f;

    for (int t = 0; t < TN; t++) {
        const int cur = t & 1;

        float zx_nxt = (tid < 256) ? __ldcg(zxp + 32 * NJ) : 0.0f;
        zxp += 32 * NJ;

        // warp-sliced wait on this warp's source slice (push #t-1); even warp
        // of the pair re-arms (before our push #t, which gates push #t+1)
        if (t > 0) {
            const int e = t - 1;
            const unsigned bar = (e & 1) ? mywait1 : mywait0;
            mbar_wait(bar, (unsigned)((e >> 1) & 1));
            if (rearm) mbar_expect_tx(bar, 256);
        }

        // recurrent matmul: 16 k x 2 u64 x 2 batches ([b][k] planes)
        unsigned long long a00=0, a01=0, a10=0, a11=0;
        const float2* Sp0 = (const float2*)&Ssm[cur][0][kbeg];
        const float2* Sp1 = (const float2*)&Ssm[cur][1][kbeg];
        #pragma unroll
        for (int i = 0; i < 8; i++) {
            float2 sa = Sp0[i];
            float2 sb = Sp1[i];
            unsigned long long p;
            p = pk2(sa.x); a00 = fma2(p, w[2*i][0],   a00); a01 = fma2(p, w[2*i][1],   a01);
            p = pk2(sa.y); a00 = fma2(p, w[2*i+1][0], a00); a01 = fma2(p, w[2*i+1][1], a01);
            p = pk2(sb.x); a10 = fma2(p, w[2*i][0],   a10); a11 = fma2(p, w[2*i][1],   a11);
            p = pk2(sb.y); a10 = fma2(p, w[2*i+1][0], a10); a11 = fma2(p, w[2*i+1][1], a11);
        }
        // conflict-free partial stores (lane-consecutive STS.32)
        {
            float* zr = &Zsm[cur][wid][0];
            float2 v;
            v = upk2(a00); zr[      jq]      = v.x; zr[      jq + 32] = v.y;
            v = upk2(a01); zr[      jq + 64] = v.x; zr[      jq + 96] = v.y;
            v = upk2(a10); zr[128 + jq]      = v.x; zr[128 + jq + 32] = v.y;
            v = upk2(a11); zr[128 + jq + 64] = v.x; zr[128 + jq + 96] = v.y;
        }

        __syncthreads();   // the ONLY block sync per step

        if (tid < 256) {
            // reduce 16 k-partials + input projection
            float z = zx_cur;
            #pragma unroll
            for (int g = 0; g < 16; g++) z += Zsm[cur][g][bb * 128 + jj];
            zx_cur = zx_nxt;

            // branch-free nonlinearity, gather 4 gates via shuffle
            float v = gatefn(gS * z, gA, gB);
            const int base = lane & ~3;
            float fv = __shfl_sync(0xFFFFFFFFu, v, base + 0);
            float iv = __shfl_sync(0xFFFFFFFFu, v, base + 1);
            float gv = __shfl_sync(0xFFFFFFFFu, v, base + 2);
            float ov = __shfl_sync(0xFFFFFFFFu, v, base + 3);

            // ALL lanes compute ct (warp-level MUFU cost unchanged by predication)
            float s_old = Ssm[cur][bb][u0 + uu];
            float c  = iv * gv + fv * s_old;
            float ct = tanh_fast(c);

            // assemble a float4 of 4 consecutive u's ct (same batch)
            const int b16 = lane & ~15;
            float q0 = __shfl_sync(0xFFFFFFFFu, ct, b16 + 0);
            float q1 = __shfl_sync(0xFFFFFFFFu, ct, b16 + 4);
            float q2 = __shfl_sync(0xFFFFFFFFu, ct, b16 + 8);
            float q3 = __shfl_sync(0xFFFFFFFFu, ct, b16 + 12);

            // pushers (lane%16==0): one v4 per target, staggered target order
            if ((lane & 15) == 0 && t + 1 < TN) {
                const unsigned po = pushOffB + (unsigned)(((t + 1) & 1) * 2048);
                const unsigned bo = barDelta + (unsigned)((t & 1) * 64);
                #pragma unroll
                for (int i2 = 0; i2 < 8; i2++) {
                    const int rk = (i2 + pusherId) & 7;
                    st_async_v4(m0v[rk] + po, q0, q1, q2, q3, m0v[rk] + bo);
                }
            }

            if ((tid & 3) == 0) {
                float h = ov * ct;
                outH[0]     = h;
                outH[c_off] = ct;
            }
            outH += UN;
        }
    }
}

// ---------------- launcher ---------------------------------------------------
extern "C" void kernel_launch(void* const* d_in, const int* in_sizes, int n_in,
                              void* d_out, int out_size) {
    const float* x  = (const float*)d_in[0];
    const float* h0 = (const float*)d_in[1];
    const float* Wf = (const float*)d_in[2];
    const float* Wi = (const float*)d_in[3];
    const float* Wc = (const float*)d_in[4];
    const float* Wo = (const float*)d_in[5];
    float* out = (float*)d_out;

    k_nop<<<1, 1>>>();
    k_init<<<2048, 256>>>(Wf, Wi, Wc, Wo);
    dim3 gg(NJ / 64, (TN * BN) / 64);   // (16, 2048)
    k_gemm<<<gg, 256>>>(x);
    k_rec<<<128, 512>>>(out, h0);
}